// round 1
// baseline (speedup 1.0000x reference)
#include <cuda_runtime.h>
#include <cuda_bf16.h>
#include <cstdint>

// Problem shape (fixed for this dataset):
//   pointcloud: (B=4, N=16384, 3) f32   -> d_in[0], 196608 elems
//   keys:       (M=4096, 3)       f32   -> d_in[1], 12288 elems
//   values:     (M=4096, D=64)    f32   -> d_in[2], 262144 elems
// Output (concatenated, f32):
//   feats (B,N,64) = 4194304 | ids (B,N,1) = 65536 | pointcloud = 196608
//   total = 4456448

#define BN      65536      // B*N points
#define M_KEYS  4096
#define D_FEAT  64
#define PC_ELEMS 196608

#define FEATS_OFF 0
#define IDS_OFF   4194304
#define PC_OFF    4259840

// Device scratch (no allocations allowed in kernel_launch).
__device__ float4 g_keys4[M_KEYS];   // (kx, ky, kz, ||k||^2)
__device__ int    g_ids[BN];

// ---------------------------------------------------------------------------
// Kernel 0: pack keys into float4 with precomputed ||k||^2
// ---------------------------------------------------------------------------
__global__ void prep_keys_kernel(const float* __restrict__ keys) {
    int j = blockIdx.x * blockDim.x + threadIdx.x;
    if (j < M_KEYS) {
        float kx = keys[3 * j + 0];
        float ky = keys[3 * j + 1];
        float kz = keys[3 * j + 2];
        // k_sq in same accumulation shape as reference sum over last axis
        float ksq = fmaf(kz, kz, fmaf(ky, ky, kx * kx));
        g_keys4[j] = make_float4(kx, ky, kz, ksq);
    }
}

// ---------------------------------------------------------------------------
// Kernel 1: brute-force argmin over M keys per point.
// One thread per point. Keys read with warp-uniform address (L1 broadcast).
// d2 = (p_sq - 2*cross) + k_sq   -- mirrors reference expansion & ordering.
// Strict '<' update in ascending j => first-min tie-break like jnp.argmin.
// ---------------------------------------------------------------------------
__global__ void __launch_bounds__(256) argmin_kernel(
    const float* __restrict__ pc,
    float* __restrict__ out_ids_f)
{
    int p = blockIdx.x * blockDim.x + threadIdx.x;
    if (p >= BN) return;

    float px = pc[3 * p + 0];
    float py = pc[3 * p + 1];
    float pz = pc[3 * p + 2];
    float psq = fmaf(pz, pz, fmaf(py, py, px * px));

    float best = __int_as_float(0x7f800000);  // +inf
    int   bidx = 0;

#pragma unroll 8
    for (int j = 0; j < M_KEYS; ++j) {
        float4 k = g_keys4[j];
        float cross = fmaf(pz, k.z, fmaf(py, k.y, px * k.x));
        float d2 = fmaf(-2.0f, cross, psq) + k.w;
        if (d2 < best) { best = d2; bidx = j; }
    }

    g_ids[p] = bidx;
    out_ids_f[p] = (float)bidx;
}

// ---------------------------------------------------------------------------
// Kernel 2: gather values rows into feats. One warp per point, float2/lane.
// ---------------------------------------------------------------------------
__global__ void __launch_bounds__(256) gather_kernel(
    const float* __restrict__ values,
    float* __restrict__ out_feats)
{
    int gtid = blockIdx.x * blockDim.x + threadIdx.x;
    int point = gtid >> 5;
    int lane  = gtid & 31;
    if (point >= BN) return;

    int id = g_ids[point];
    const float2* src = reinterpret_cast<const float2*>(values + (size_t)id * D_FEAT);
    float2* dst = reinterpret_cast<float2*>(out_feats + (size_t)point * D_FEAT);
    dst[lane] = src[lane];  // 32 lanes x 8B = 256B = one row of 64 f32
}

// ---------------------------------------------------------------------------
extern "C" void kernel_launch(void* const* d_in, const int* in_sizes, int n_in,
                              void* d_out, int out_size) {
    const float* pc     = (const float*)d_in[0];
    const float* keys   = (const float*)d_in[1];
    const float* values = (const float*)d_in[2];
    float* out = (float*)d_out;

    prep_keys_kernel<<<(M_KEYS + 255) / 256, 256>>>(keys);
    argmin_kernel<<<(BN + 255) / 256, 256>>>(pc, out + IDS_OFF);
    gather_kernel<<<(BN * 32 + 255) / 256, 256>>>(values, out + FEATS_OFF);
    cudaMemcpyAsync(out + PC_OFF, pc, PC_ELEMS * sizeof(float),
                    cudaMemcpyDeviceToDevice, 0);
}

// round 2
// speedup vs baseline: 2.4138x; 2.4138x over previous
#include <cuda_runtime.h>
#include <cuda_bf16.h>
#include <cstdint>

// Shapes (fixed): pointcloud (4,16384,3) f32; keys (4096,3) f32; values (4096,64) f32
// Output f32: feats (65536,64) | ids (65536) | pointcloud (196608) = 4456448 elems

#define BN       65536
#define M_KEYS   4096
#define D_FEAT   64
#define PC_ELEMS 196608

#define FEATS_OFF 0
#define IDS_OFF   4194304
#define PC_OFF    4259840

#define NSLICE   4
#define SLICE_M  (M_KEYS / NSLICE)   // 1024 keys per slice

// Device scratch (no allocs allowed in kernel_launch).
__device__ float4 g_keys4[M_KEYS];                 // (kx, ky, kz, ||k||^2)
__device__ unsigned long long g_best[BN];          // (ordered_d2_bits << 32) | key_idx

// ---------------------------------------------------------------------------
// Kernel 0: pack keys into float4 with precomputed ||k||^2
// ---------------------------------------------------------------------------
__global__ void prep_keys_kernel(const float* __restrict__ keys) {
    int j = blockIdx.x * blockDim.x + threadIdx.x;
    if (j < M_KEYS) {
        float kx = keys[3 * j + 0];
        float ky = keys[3 * j + 1];
        float kz = keys[3 * j + 2];
        float ksq = fmaf(kz, kz, fmaf(ky, ky, kx * kx));
        g_keys4[j] = make_float4(kx, ky, kz, ksq);
    }
}

// ---------------------------------------------------------------------------
// Kernel 1: init packed best to +inf
// ---------------------------------------------------------------------------
__global__ void init_best_kernel() {
    int p = blockIdx.x * blockDim.x + threadIdx.x;
    if (p < BN) g_best[p] = 0xFFFFFFFFFFFFFFFFULL;
}

// ---------------------------------------------------------------------------
// Kernel 2: sliced argmin. blockIdx.x -> 256-point tile, blockIdx.y -> key slice.
// Keys slice staged in shared memory; LDS address is warp-uniform (broadcast).
// Per-pair arithmetic identical to the R1 kernel that matched exactly:
//   cross = fmaf(pz,kz, fmaf(py,ky, px*kx))
//   d2    = fmaf(-2, cross, psq) + ksq
// Cross-slice merge: lexicographic u64 atomicMin on (ordered_bits(d2), j)
// == global first-min semantics (jnp.argmin tie-break).
// ---------------------------------------------------------------------------
__global__ void __launch_bounds__(256) argmin_slice_kernel(
    const float* __restrict__ pc)
{
    __shared__ float4 sk[SLICE_M];

    const int base = blockIdx.y * SLICE_M;

    // Stage this block's key slice (16KB) into shared.
#pragma unroll
    for (int i = threadIdx.x; i < SLICE_M; i += 256)
        sk[i] = g_keys4[base + i];
    __syncthreads();

    const int p = blockIdx.x * 256 + threadIdx.x;

    float px = pc[3 * p + 0];
    float py = pc[3 * p + 1];
    float pz = pc[3 * p + 2];
    float psq = fmaf(pz, pz, fmaf(py, py, px * px));

    float best = __int_as_float(0x7f800000);  // +inf
    int   bidx = base;

#pragma unroll 8
    for (int i = 0; i < SLICE_M; ++i) {
        float4 k = sk[i];
        float cross = fmaf(pz, k.z, fmaf(py, k.y, px * k.x));
        float d2 = fmaf(-2.0f, cross, psq) + k.w;
        if (d2 < best) { best = d2; bidx = base + i; }
    }

    // Float -> order-preserving uint (handles any sign), once per slice.
    unsigned u = __float_as_uint(best);
    u = (u & 0x80000000u) ? ~u : (u | 0x80000000u);
    unsigned long long packed = ((unsigned long long)u << 32) | (unsigned)bidx;

    atomicMin(&g_best[p], packed);
}

// ---------------------------------------------------------------------------
// Kernel 3: gather values rows into feats + emit ids. One warp per point.
// ---------------------------------------------------------------------------
__global__ void __launch_bounds__(256) gather_kernel(
    const float* __restrict__ values,
    float* __restrict__ out_feats,
    float* __restrict__ out_ids_f)
{
    int gtid = blockIdx.x * blockDim.x + threadIdx.x;
    int point = gtid >> 5;
    int lane  = gtid & 31;
    if (point >= BN) return;

    int id = (int)(g_best[point] & 0xFFFFFFFFu);   // broadcast load
    if (lane == 0) out_ids_f[point] = (float)id;

    const float2* src = reinterpret_cast<const float2*>(values + (size_t)id * D_FEAT);
    float2* dst = reinterpret_cast<float2*>(out_feats + (size_t)point * D_FEAT);
    dst[lane] = src[lane];
}

// ---------------------------------------------------------------------------
extern "C" void kernel_launch(void* const* d_in, const int* in_sizes, int n_in,
                              void* d_out, int out_size) {
    const float* pc     = (const float*)d_in[0];
    const float* keys   = (const float*)d_in[1];
    const float* values = (const float*)d_in[2];
    float* out = (float*)d_out;

    prep_keys_kernel<<<(M_KEYS + 255) / 256, 256>>>(keys);
    init_best_kernel<<<(BN + 255) / 256, 256>>>();

    dim3 grid(BN / 256, NSLICE);
    argmin_slice_kernel<<<grid, 256>>>(pc);

    gather_kernel<<<(BN * 32 + 255) / 256, 256>>>(values, out + FEATS_OFF, out + IDS_OFF);
    cudaMemcpyAsync(out + PC_OFF, pc, PC_ELEMS * sizeof(float),
                    cudaMemcpyDeviceToDevice, 0);
}

// round 3
// speedup vs baseline: 3.0757x; 1.2742x over previous
#include <cuda_runtime.h>
#include <cuda_bf16.h>
#include <cstdint>

// Shapes (fixed): pointcloud (4,16384,3) f32; keys (4096,3) f32; values (4096,64) f32
// Output f32: feats (65536,64) | ids (65536) | pointcloud (196608) = 4456448 elems

#define BN       65536
#define M_KEYS   4096
#define D_FEAT   64
#define PC_ELEMS 196608

#define FEATS_OFF 0
#define IDS_OFF   4194304
#define PC_OFF    4259840

#define NSLICE   4
#define SLICE_M  (M_KEYS / NSLICE)      // 1024 keys per slice
#define SLICE_P  (SLICE_M / 2)          // 512 key-pairs per slice

// ---- packed f32x2 helpers (each half = exact scalar fp32 op) ----
#define FMA2(out, a, b, c) \
    asm("fma.rn.f32x2 %0, %1, %2, %3;" : "=l"(out) : "l"(a), "l"(b), "l"(c))
#define MUL2(out, a, b) \
    asm("mul.rn.f32x2 %0, %1, %2;" : "=l"(out) : "l"(a), "l"(b))
#define ADD2(out, a, b) \
    asm("add.rn.f32x2 %0, %1, %2;" : "=l"(out) : "l"(a), "l"(b))
#define PACK2(out, lo, hi) \
    asm("mov.b64 %0, {%1, %2};" : "=l"(out) : "f"(lo), "f"(hi))
#define UNPACK2(lo, hi, in) \
    asm("mov.b64 {%0, %1}, %2;" : "=f"(lo), "=f"(hi) : "l"(in))

// Key-pair struct: a = (kx0,kx1,ky0,ky1), b = (kz0,kz1,ksq0,ksq1)
struct KeyPair { float4 a; float4 b; };

// Device scratch (no allocs allowed in kernel_launch).
__device__ KeyPair g_kp[M_KEYS / 2];
__device__ unsigned long long g_best[BN];   // (ordered_d2_bits << 32) | key_idx

// ---------------------------------------------------------------------------
// Kernel 0: fused prep (key pairs + ||k||^2) and best-init.
// ---------------------------------------------------------------------------
__global__ void __launch_bounds__(256) prep_kernel(const float* __restrict__ keys) {
    int t = blockIdx.x * blockDim.x + threadIdx.x;
    if (t < BN) g_best[t] = 0xFFFFFFFFFFFFFFFFULL;
    if (t < M_KEYS / 2) {
        int j0 = 2 * t;
        float kx0 = keys[3*j0+0], ky0 = keys[3*j0+1], kz0 = keys[3*j0+2];
        float kx1 = keys[3*j0+3], ky1 = keys[3*j0+4], kz1 = keys[3*j0+5];
        float q0 = fmaf(kz0, kz0, fmaf(ky0, ky0, kx0 * kx0));
        float q1 = fmaf(kz1, kz1, fmaf(ky1, ky1, kx1 * kx1));
        KeyPair kp;
        kp.a = make_float4(kx0, kx1, ky0, ky1);
        kp.b = make_float4(kz0, kz1, q0, q1);
        g_kp[t] = kp;
    }
}

// ---------------------------------------------------------------------------
// Kernel 1: sliced argmin, 2 keys per iteration via packed f32x2.
// Per-half arithmetic identical to the bit-exact R1/R2 form:
//   cross = fmaf(pz,kz, fmaf(py,ky, px*kx));  d2 = fmaf(-2,cross,psq) + ksq
// Strict '<' in ascending key order => first-min tie-break (jnp.argmin).
// Cross-slice merge via lexicographic u64 atomicMin on (ordered_bits, idx).
// ---------------------------------------------------------------------------
__global__ void __launch_bounds__(256) argmin_slice_kernel(
    const float* __restrict__ pc)
{
    __shared__ KeyPair sk[SLICE_P];   // 16KB

    const int base = blockIdx.y * SLICE_M;
    const int pbase = blockIdx.y * SLICE_P;

#pragma unroll
    for (int i = threadIdx.x; i < SLICE_P; i += 256)
        sk[i] = g_kp[pbase + i];
    __syncthreads();

    const int p = blockIdx.x * 256 + threadIdx.x;

    float px = pc[3 * p + 0];
    float py = pc[3 * p + 1];
    float pz = pc[3 * p + 2];
    float psq = fmaf(pz, pz, fmaf(py, py, px * px));

    unsigned long long px2, py2, pz2, psq2, n22;
    PACK2(px2, px, px);
    PACK2(py2, py, py);
    PACK2(pz2, pz, pz);
    PACK2(psq2, psq, psq);
    PACK2(n22, -2.0f, -2.0f);

    float best = __int_as_float(0x7f800000);  // +inf
    int   bidx = base;

#pragma unroll 8
    for (int i = 0; i < SLICE_P; ++i) {
        float4 a = sk[i].a;   // kx0,kx1,ky0,ky1
        float4 b = sk[i].b;   // kz0,kz1,q0,q1
        unsigned long long kx01, ky01, kz01, q01;
        PACK2(kx01, a.x, a.y);
        PACK2(ky01, a.z, a.w);
        PACK2(kz01, b.x, b.y);
        PACK2(q01,  b.z, b.w);

        unsigned long long c01, t01, d01;
        MUL2(c01, px2, kx01);          // px*kx
        FMA2(c01, py2, ky01, c01);     // fma(py,ky, .)
        FMA2(c01, pz2, kz01, c01);     // fma(pz,kz, .)
        FMA2(t01, n22, c01, psq2);     // fma(-2, cross, psq)
        ADD2(d01, t01, q01);           // + ksq

        float d0, d1;
        UNPACK2(d0, d1, d01);
        int j0 = base + 2 * i;
        if (d0 < best) { best = d0; bidx = j0; }
        if (d1 < best) { best = d1; bidx = j0 + 1; }
    }

    // Float -> order-preserving uint (handles rounding-negative d2).
    unsigned u = __float_as_uint(best);
    u = (u & 0x80000000u) ? ~u : (u | 0x80000000u);
    unsigned long long packed = ((unsigned long long)u << 32) | (unsigned)bidx;

    atomicMin(&g_best[p], packed);
}

// ---------------------------------------------------------------------------
// Kernel 2: gather values rows into feats + emit ids. 16 threads/point, f4.
// ---------------------------------------------------------------------------
__global__ void __launch_bounds__(256) gather_kernel(
    const float* __restrict__ values,
    float* __restrict__ out_feats,
    float* __restrict__ out_ids_f)
{
    int t = blockIdx.x * blockDim.x + threadIdx.x;
    int point = t >> 4;
    int q     = t & 15;
    if (point >= BN) return;

    int id = (int)(g_best[point] & 0xFFFFFFFFu);   // broadcast load
    if (q == 0) out_ids_f[point] = (float)id;

    const float4* src = reinterpret_cast<const float4*>(values + (size_t)id * D_FEAT);
    float4* dst = reinterpret_cast<float4*>(out_feats + (size_t)point * D_FEAT);
    dst[q] = src[q];
}

// ---------------------------------------------------------------------------
extern "C" void kernel_launch(void* const* d_in, const int* in_sizes, int n_in,
                              void* d_out, int out_size) {
    const float* pc     = (const float*)d_in[0];
    const float* keys   = (const float*)d_in[1];
    const float* values = (const float*)d_in[2];
    float* out = (float*)d_out;

    prep_kernel<<<(BN + 255) / 256, 256>>>(keys);

    dim3 grid(BN / 256, NSLICE);
    argmin_slice_kernel<<<grid, 256>>>(pc);

    gather_kernel<<<(BN * 16 + 255) / 256, 256>>>(values, out + FEATS_OFF, out + IDS_OFF);
    cudaMemcpyAsync(out + PC_OFF, pc, PC_ELEMS * sizeof(float),
                    cudaMemcpyDeviceToDevice, 0);
}